// round 8
// baseline (speedup 1.0000x reference)
#include <cuda_runtime.h>
#include <cuda_bf16.h>
#include <cstdint>

// HeteLinear: out[n] = x[n] @ W[x_type[n]] + b[x_type[n]]
// N=262144, IN=OUT=128, T=8, fp32.
// Grouped GEMM on mma.sync HMMA bf16, 3-product bf16 hi/lo split.
// Warp-specialized persistent CTAs: 8 consumer warps (m32xn64, MMA+epilogue)
// + 8 producer warps (gather/convert/stage next tile). One syncthreads per tile.
// R8: producer gather is BATCHED (all 16 LDG.128 in flight before any convert)
// to restore memory-level parallelism (R7 had MLP=1 on the gather path).

#define NMAX    262144
#define TT      8
#define DIM     128
#define TILE_M  128
#define GT      512
#define NB      256                 // compaction blocks
#define BT      256
#define PREPB   32                  // prep blocks appended to k_pre grid
#define LDE     136                 // padded image row (bf16 elems): 272B
#define LDB     (LDE * 2)
#define IMG_BYTES (DIM * LDE * 2)   // 34816
#define IMG_U4    (IMG_BYTES / 16)

// gemm smem layout (bytes)
#define S_A0    0
#define A_LO    34816
#define S_A1    69632
#define S_WHI   139264
#define S_WLO   174080
#define S_BIAS  208896              // float[2][128]
#define S_ROWS  209920              // int[2][128]
#define S_TOTAL 210944

// ---------------- device globals ----------------
__device__ int g_bcount[TT * NB];
__device__ int g_bbase[TT * NB];
__device__ int g_offsets[TT + 1];
__device__ int g_tileBase[TT + 1];
__device__ int g_perm[NMAX];
__device__ __align__(16) uint8_t g_Whi[TT][IMG_BYTES];
__device__ __align__(16) uint8_t g_Wlo[TT][IMG_BYTES];

// ---------------- helpers ----------------
__device__ __forceinline__ uint32_t smem_u32(const void* p) {
    uint32_t a;
    asm("{ .reg .u64 t; cvta.to.shared.u64 t, %1; cvt.u32.u64 %0, t; }" : "=r"(a) : "l"(p));
    return a;
}
__device__ __forceinline__ void ldsm4(uint32_t (&r)[4], uint32_t addr) {
    asm volatile("ldmatrix.sync.aligned.m8n8.x4.shared.b16 {%0,%1,%2,%3}, [%4];"
                 : "=r"(r[0]), "=r"(r[1]), "=r"(r[2]), "=r"(r[3]) : "r"(addr));
}
__device__ __forceinline__ void mma16816(float (&c)[4], const uint32_t (&a)[4],
                                         uint32_t b0, uint32_t b1) {
    asm volatile("mma.sync.aligned.m16n8k16.row.col.f32.bf16.bf16.f32 "
                 "{%0,%1,%2,%3}, {%4,%5,%6,%7}, {%8,%9}, {%0,%1,%2,%3};"
                 : "+f"(c[0]), "+f"(c[1]), "+f"(c[2]), "+f"(c[3])
                 : "r"(a[0]), "r"(a[1]), "r"(a[2]), "r"(a[3]), "r"(b0), "r"(b1));
}
__device__ __forceinline__ uint32_t pkbf(__nv_bfloat16 a, __nv_bfloat16 b) {
    return (uint32_t)__bfloat16_as_ushort(a) | ((uint32_t)__bfloat16_as_ushort(b) << 16);
}

// ---------------- pre: count (blocks 0..NB-1) + W prep (blocks NB..NB+31) ----------------
__global__ void k_pre(const int* __restrict__ xt, const float* __restrict__ W,
                      int n, int seg) {
    __shared__ float ws[32][129];
    const int tid = threadIdx.x, lane = tid & 31;

    if (blockIdx.x < NB) {
        const int bid = blockIdx.x;
        const int start = bid * seg, end = min(start + seg, n);
        __shared__ int cnt[TT];
        if (tid < TT) cnt[tid] = 0;
        __syncthreads();
        int rc[TT];
        #pragma unroll
        for (int t = 0; t < TT; t++) rc[t] = 0;
        const int rounds = (seg + BT - 1) / BT;
        for (int r = 0; r < rounds; r++) {
            int i = start + r * BT + tid;
            int m = (i < end) ? xt[i] : -1;
            #pragma unroll
            for (int t = 0; t < TT; t++)
                rc[t] += __popc(__ballot_sync(0xffffffffu, m == t));
        }
        if (lane == 0) {
            #pragma unroll
            for (int t = 0; t < TT; t++) atomicAdd(&cnt[t], rc[t]);
        }
        __syncthreads();
        if (tid < TT) g_bcount[tid * NB + bid] = cnt[tid];
    } else {
        const int sl = blockIdx.x - NB;
        const int t  = sl >> 2;
        const int kb = (sl & 3) * 32;
        #pragma unroll
        for (int j = 0; j < 16; j++) {
            int idx = tid + j * 256;
            int r = idx >> 7, col = idx & 127;
            ws[r][col] = W[((size_t)t * DIM + kb + r) * DIM + col];
        }
        __syncthreads();
        const int kk = tid & 15;
        #pragma unroll
        for (int j = 0; j < 8; j++) {
            int nn = (tid >> 4) + j * 16;
            float w0 = ws[2 * kk][nn], w1 = ws[2 * kk + 1][nn];
            __nv_bfloat16 h0 = __float2bfloat16_rn(w0), h1 = __float2bfloat16_rn(w1);
            __nv_bfloat16 l0 = __float2bfloat16_rn(w0 - __bfloat162float(h0));
            __nv_bfloat16 l1 = __float2bfloat16_rn(w1 - __bfloat162float(h1));
            uint32_t off = (uint32_t)nn * LDB + (uint32_t)(kb + 2 * kk) * 2;
            *(uint32_t*)(g_Whi[t] + off) = pkbf(h0, h1);
            *(uint32_t*)(g_Wlo[t] + off) = pkbf(l0, l1);
        }
    }
}

__global__ void k_scan() {
    const int tid = threadIdx.x, warp = tid >> 5, lane = tid & 31;
    __shared__ int tot[TT];
    if (warp < TT) {
        int s = 0;
        #pragma unroll
        for (int c = 0; c < NB / 32; c++) s += g_bcount[warp * NB + c * 32 + lane];
        #pragma unroll
        for (int o = 16; o; o >>= 1) s += __shfl_xor_sync(0xffffffffu, s, o);
        if (lane == 0) tot[warp] = s;
    }
    __syncthreads();
    if (tid == 0) {
        int o = 0, tbv = 0;
        g_offsets[0] = 0; g_tileBase[0] = 0;
        for (int t = 0; t < TT; t++) {
            o += tot[t];
            g_offsets[t + 1] = o;
            tbv += (tot[t] + TILE_M - 1) / TILE_M;
            g_tileBase[t + 1] = tbv;
        }
    }
    __syncthreads();
    if (warp < TT) {
        int run = g_offsets[warp];
        #pragma unroll
        for (int c = 0; c < NB / 32; c++) {
            int v = g_bcount[warp * NB + c * 32 + lane];
            int xsc = v;
            #pragma unroll
            for (int o = 1; o < 32; o <<= 1) {
                int y = __shfl_up_sync(0xffffffffu, xsc, o);
                if (lane >= o) xsc += y;
            }
            g_bbase[warp * NB + c * 32 + lane] = run + xsc - v;
            run += __shfl_sync(0xffffffffu, xsc, 31);
        }
    }
}

__global__ void k_scatter(const int* __restrict__ xt, int n, int seg) {
    const int bid = blockIdx.x, tid = threadIdx.x, lane = tid & 31;
    const int start = bid * seg, end = min(start + seg, n);
    __shared__ int cur[TT];
    if (tid < TT) cur[tid] = g_bbase[tid * NB + bid];
    __syncthreads();
    const int rounds = (seg + BT - 1) / BT;
    for (int r = 0; r < rounds; r++) {
        int i = start + r * BT + tid;
        int m = (i < end) ? xt[i] : -1;
        #pragma unroll
        for (int t = 0; t < TT; t++) {
            unsigned mask = __ballot_sync(0xffffffffu, m == t);
            if (mask) {
                int leader = __ffs(mask) - 1;
                int pos = 0;
                if (lane == leader) pos = atomicAdd(&cur[t], __popc(mask));
                pos = __shfl_sync(0xffffffffu, pos, leader);
                if (m == t) g_perm[pos + __popc(mask & ((1u << lane) - 1u))] = i;
            }
        }
    }
}

// ---------------- GEMM ----------------
__device__ __forceinline__ void copyW(int t, uint8_t* smem, int tid) {
    const uint4* shi = (const uint4*)g_Whi[t];
    const uint4* slo = (const uint4*)g_Wlo[t];
    uint4* dhi = (uint4*)(smem + S_WHI);
    uint4* dlo = (uint4*)(smem + S_WLO);
    #pragma unroll 4
    for (int i = tid; i < IMG_U4; i += GT) { dhi[i] = shi[i]; dlo[i] = slo[i]; }
}

// convert+store one x row (512B, lane-sliced) into hi/lo images at image row ir
__device__ __forceinline__ void cvtRow(uint4 vv, uint8_t* dst, int ir, int lane) {
    float4 f = *(const float4*)&vv;
    __nv_bfloat16 h0 = __float2bfloat16_rn(f.x), h1 = __float2bfloat16_rn(f.y);
    __nv_bfloat16 h2 = __float2bfloat16_rn(f.z), h3 = __float2bfloat16_rn(f.w);
    __nv_bfloat16 l0 = __float2bfloat16_rn(f.x - __bfloat162float(h0));
    __nv_bfloat16 l1 = __float2bfloat16_rn(f.y - __bfloat162float(h1));
    __nv_bfloat16 l2 = __float2bfloat16_rn(f.z - __bfloat162float(h2));
    __nv_bfloat16 l3 = __float2bfloat16_rn(f.w - __bfloat162float(h3));
    uint32_t offB = (uint32_t)ir * LDB + (uint32_t)lane * 8;
    *(uint2*)(dst + offB)        = make_uint2(pkbf(h0, h1), pkbf(h2, h3));
    *(uint2*)(dst + A_LO + offB) = make_uint2(pkbf(l0, l1), pkbf(l2, l3));
}

__global__ __launch_bounds__(GT, 1)
void k_gemm(const float* __restrict__ x,
            const float* __restrict__ b,
            float* __restrict__ out)
{
    extern __shared__ uint8_t smem[];
    const int tid  = threadIdx.x;
    const int warp = tid >> 5;
    const int lane = tid & 31;
    const bool consumer = (warp < 8);
    const int mw = warp & 3;        // consumer: m chunk of 32 rows
    const int nh = (warp >> 2) & 1; // consumer: n half (64 cols)
    const int pw = warp - 8;        // producer index 0..7

    const uint32_t sbase = smem_u32(smem);
    float* biasS = (float*)(smem + S_BIAS);
    int*   rowsS = (int*)(smem + S_ROWS);

    int tb[TT + 1], off[TT + 1];
    #pragma unroll
    for (int i = 0; i <= TT; i++) { tb[i] = g_tileBase[i]; off[i] = g_offsets[i]; }

    const int total = tb[TT];
    const int per   = (total + gridDim.x - 1) / gridDim.x;
    const int i0    = blockIdx.x * per;
    const int i1    = min(i0 + per, total);
    if (i0 >= i1) return;

    // consumer ldmatrix lane offsets (mapping proven R3-R7)
    const uint32_t aOff = (uint32_t)(mw * 32 + (lane & 15)) * LDB + (uint32_t)(lane >> 4) * 16;
    const uint32_t bOff = (uint32_t)(nh * 64 + (lane & 7) + ((lane & 16) ? 8 : 0)) * LDB
                        + (uint32_t)((lane >> 3) & 1) * 16;

    float acc[2][8][4];
    #pragma unroll
    for (int s = 0; s < 2; s++)
        #pragma unroll
        for (int j = 0; j < 8; j++)
            #pragma unroll
            for (int q = 0; q < 4; q++) acc[s][j][q] = 0.f;

    int cur_type;

    // ---- prologue: stage tile i0 (all warps; each stages 8 rows, batched LDG) ----
    {
        int t = 0;
        #pragma unroll
        for (int s = 1; s < TT; s++) t += (i0 >= tb[s]);
        copyW(t, smem, tid); cur_type = t;
        int segStart = off[t] + (i0 - tb[t]) * TILE_M;
        int nr       = min(TILE_M, off[t + 1] - segStart);
        if (tid < DIM) {
            rowsS[(i0 & 1) * DIM + tid] = (tid < nr) ? g_perm[segStart + tid] : -1;
            biasS[(i0 & 1) * DIM + tid] = b[(size_t)t * DIM + tid];
        }
        int rown = -1;
        if (lane < 8) {
            int idx = warp * 8 + lane;
            rown = (idx < nr) ? g_perm[segStart + idx] : -1;
        }
        uint4 v[8];
        #pragma unroll
        for (int rr = 0; rr < 8; rr++) {
            int row = __shfl_sync(0xffffffffu, rown, rr);
            v[rr] = make_uint4(0, 0, 0, 0);
            if (row >= 0) v[rr] = ((const uint4*)x)[(size_t)row * 32 + lane];
        }
        uint8_t* dst = smem + ((i0 & 1) ? S_A1 : S_A0);
        #pragma unroll
        for (int rr = 0; rr < 8; rr++) cvtRow(v[rr], dst, warp * 8 + rr, lane);
        __syncthreads();
    }

    for (int i = i0; i < i1; i++) {
        const int cb = i & 1;
        int nt = cur_type;
        if (i + 1 < i1) {
            nt = 0;
            #pragma unroll
            for (int s = 1; s < TT; s++) nt += ((i + 1) >= tb[s]);
        }

        if (consumer) {
            // ---- MMA: 3 products x 8 k-steps, m32 x n64 ----
            #pragma unroll
            for (int p = 0; p < 3; p++) {
                const uint32_t aBase = sbase + (cb ? S_A1 : S_A0) + (p == 2 ? A_LO : 0) + aOff;
                const uint32_t bBase = sbase + (p == 1 ? S_WLO : S_WHI) + bOff;
                #pragma unroll
                for (int kk = 0; kk < 8; kk++) {
                    uint32_t a0[4], a1[4];
                    ldsm4(a0, aBase + kk * 32);
                    ldsm4(a1, aBase + 16 * LDB + kk * 32);
                    #pragma unroll
                    for (int jj = 0; jj < 4; jj++) {
                        uint32_t bb[4];
                        ldsm4(bb, bBase + (uint32_t)jj * (16 * LDB) + kk * 32);
                        mma16816(acc[0][2 * jj],     a0, bb[0], bb[1]);
                        mma16816(acc[0][2 * jj + 1], a0, bb[2], bb[3]);
                        mma16816(acc[1][2 * jj],     a1, bb[0], bb[1]);
                        mma16816(acc[1][2 * jj + 1], a1, bb[2], bb[3]);
                    }
                }
            }
            // ---- epilogue (before sync: rowsS/biasS slot cb is stable) ----
            const int g = lane >> 2;
            const float* bS = biasS + cb * DIM;
            #pragma unroll
            for (int s = 0; s < 2; s++) {
                const int rbase = mw * 32 + s * 16 + g;
                const int r1 = rowsS[cb * DIM + rbase];
                const int r2 = rowsS[cb * DIM + rbase + 8];
                #pragma unroll
                for (int j = 0; j < 8; j++) {
                    int col = nh * 64 + j * 8 + (lane & 3) * 2;
                    float2 bb = *(const float2*)(bS + col);
                    if (r1 >= 0)
                        *(float2*)(out + (size_t)r1 * DIM + col) =
                            make_float2(acc[s][j][0] + bb.x, acc[s][j][1] + bb.y);
                    if (r2 >= 0)
                        *(float2*)(out + (size_t)r2 * DIM + col) =
                            make_float2(acc[s][j][2] + bb.x, acc[s][j][3] + bb.y);
                    acc[s][j][0] = acc[s][j][1] = acc[s][j][2] = acc[s][j][3] = 0.f;
                }
            }
        } else if (i + 1 < i1) {
            // ---- producer: stage tile i+1 into buffer cb^1 (BATCHED gather) ----
            int segStart = off[nt] + (i + 1 - tb[nt]) * TILE_M;
            int nr       = min(TILE_M, off[nt + 1] - segStart);
            int ptid = tid - 256;
            if (ptid < DIM) {
                rowsS[(cb ^ 1) * DIM + ptid] = (ptid < nr) ? g_perm[segStart + ptid] : -1;
                biasS[(cb ^ 1) * DIM + ptid] = b[(size_t)nt * DIM + ptid];
            }
            int rown = -1;
            if (lane < 16) {
                int idx = pw * 16 + lane;
                rown = (idx < nr) ? g_perm[segStart + idx] : -1;
            }
            // phase 1: all 16 LDG.128 in flight (MLP=16)
            uint4 v[16];
            #pragma unroll
            for (int rr = 0; rr < 16; rr++) {
                int row = __shfl_sync(0xffffffffu, rown, rr);
                v[rr] = make_uint4(0, 0, 0, 0);
                if (row >= 0) v[rr] = ((const uint4*)x)[(size_t)row * 32 + lane];
            }
            // phase 2: convert + store
            uint8_t* dst = smem + ((cb ^ 1) ? S_A1 : S_A0);
            #pragma unroll
            for (int rr = 0; rr < 16; rr++) cvtRow(v[rr], dst, pw * 16 + rr, lane);
        }

        __syncthreads();
        if (nt != cur_type) {     // rare W reload: consumers done with tile i now
            copyW(nt, smem, tid);
            cur_type = nt;
            __syncthreads();
        }
    }
}

// ---------------- launch ----------------
extern "C" void kernel_launch(void* const* d_in, const int* in_sizes, int n_in,
                              void* d_out, int out_size)
{
    const float* x      = (const float*)d_in[0];
    const int*   x_type = (const int*)d_in[1];
    const float* W      = (const float*)d_in[2];
    const float* b      = (const float*)d_in[3];
    float*       out    = (float*)d_out;

    const int N   = in_sizes[1];
    const int seg = (N + NB - 1) / NB;

    static int nsm = 0;
    if (!nsm) {
        cudaDeviceGetAttribute(&nsm, cudaDevAttrMultiProcessorCount, 0);
        if (nsm <= 0) nsm = 148;
        cudaFuncSetAttribute(k_gemm, cudaFuncAttributeMaxDynamicSharedMemorySize, S_TOTAL);
    }

    k_pre<<<NB + PREPB, BT>>>(x_type, W, N, seg);
    k_scan<<<1, 256>>>();
    k_scatter<<<NB, BT>>>(x_type, N, seg);
    k_gemm<<<nsm, GT, S_TOTAL>>>(x, b, out);
}

// round 9
// speedup vs baseline: 1.0053x; 1.0053x over previous
#include <cuda_runtime.h>
#include <cuda_bf16.h>
#include <cstdint>

// HeteLinear: out[n] = x[n] @ W[x_type[n]] + b[x_type[n]]
// N=262144, IN=OUT=128, T=8, fp32.
// Grouped GEMM on mma.sync HMMA bf16, 3-product bf16 hi/lo split.
// Warp-specialized persistent CTAs: 8 consumer warps (m32xn64, MMA+epilogue)
// + 8 producer warps (gather/convert/stage next tile). One syncthreads per tile.
// R9: producer gather in TWO WAVES of 8 batched LDG.128 (v[8] = 32 regs).
// R8's v[16] batch (64 regs) spilled under the 128-reg cap and regressed;
// R7's fused form had MLP=1. This gets MLP=8 without spills.

#define NMAX    262144
#define TT      8
#define DIM     128
#define TILE_M  128
#define GT      512
#define NB      256                 // compaction blocks
#define BT      256
#define PREPB   32                  // prep blocks appended to k_pre grid
#define LDE     136                 // padded image row (bf16 elems): 272B
#define LDB     (LDE * 2)
#define IMG_BYTES (DIM * LDE * 2)   // 34816
#define IMG_U4    (IMG_BYTES / 16)

// gemm smem layout (bytes)
#define S_A0    0
#define A_LO    34816
#define S_A1    69632
#define S_WHI   139264
#define S_WLO   174080
#define S_BIAS  208896              // float[2][128]
#define S_ROWS  209920              // int[2][128]
#define S_TOTAL 210944

// ---------------- device globals ----------------
__device__ int g_bcount[TT * NB];
__device__ int g_bbase[TT * NB];
__device__ int g_offsets[TT + 1];
__device__ int g_tileBase[TT + 1];
__device__ int g_perm[NMAX];
__device__ __align__(16) uint8_t g_Whi[TT][IMG_BYTES];
__device__ __align__(16) uint8_t g_Wlo[TT][IMG_BYTES];

// ---------------- helpers ----------------
__device__ __forceinline__ uint32_t smem_u32(const void* p) {
    uint32_t a;
    asm("{ .reg .u64 t; cvta.to.shared.u64 t, %1; cvt.u32.u64 %0, t; }" : "=r"(a) : "l"(p));
    return a;
}
__device__ __forceinline__ void ldsm4(uint32_t (&r)[4], uint32_t addr) {
    asm volatile("ldmatrix.sync.aligned.m8n8.x4.shared.b16 {%0,%1,%2,%3}, [%4];"
                 : "=r"(r[0]), "=r"(r[1]), "=r"(r[2]), "=r"(r[3]) : "r"(addr));
}
__device__ __forceinline__ void mma16816(float (&c)[4], const uint32_t (&a)[4],
                                         uint32_t b0, uint32_t b1) {
    asm volatile("mma.sync.aligned.m16n8k16.row.col.f32.bf16.bf16.f32 "
                 "{%0,%1,%2,%3}, {%4,%5,%6,%7}, {%8,%9}, {%0,%1,%2,%3};"
                 : "+f"(c[0]), "+f"(c[1]), "+f"(c[2]), "+f"(c[3])
                 : "r"(a[0]), "r"(a[1]), "r"(a[2]), "r"(a[3]), "r"(b0), "r"(b1));
}
__device__ __forceinline__ uint32_t pkbf(__nv_bfloat16 a, __nv_bfloat16 b) {
    return (uint32_t)__bfloat16_as_ushort(a) | ((uint32_t)__bfloat16_as_ushort(b) << 16);
}

// ---------------- pre: count (blocks 0..NB-1) + W prep (blocks NB..NB+31) ----------------
__global__ void k_pre(const int* __restrict__ xt, const float* __restrict__ W,
                      int n, int seg) {
    __shared__ float ws[32][129];
    const int tid = threadIdx.x, lane = tid & 31;

    if (blockIdx.x < NB) {
        const int bid = blockIdx.x;
        const int start = bid * seg, end = min(start + seg, n);
        __shared__ int cnt[TT];
        if (tid < TT) cnt[tid] = 0;
        __syncthreads();
        int rc[TT];
        #pragma unroll
        for (int t = 0; t < TT; t++) rc[t] = 0;
        const int rounds = (seg + BT - 1) / BT;
        for (int r = 0; r < rounds; r++) {
            int i = start + r * BT + tid;
            int m = (i < end) ? xt[i] : -1;
            #pragma unroll
            for (int t = 0; t < TT; t++)
                rc[t] += __popc(__ballot_sync(0xffffffffu, m == t));
        }
        if (lane == 0) {
            #pragma unroll
            for (int t = 0; t < TT; t++) atomicAdd(&cnt[t], rc[t]);
        }
        __syncthreads();
        if (tid < TT) g_bcount[tid * NB + bid] = cnt[tid];
    } else {
        const int sl = blockIdx.x - NB;
        const int t  = sl >> 2;
        const int kb = (sl & 3) * 32;
        #pragma unroll
        for (int j = 0; j < 16; j++) {
            int idx = tid + j * 256;
            int r = idx >> 7, col = idx & 127;
            ws[r][col] = W[((size_t)t * DIM + kb + r) * DIM + col];
        }
        __syncthreads();
        const int kk = tid & 15;
        #pragma unroll
        for (int j = 0; j < 8; j++) {
            int nn = (tid >> 4) + j * 16;
            float w0 = ws[2 * kk][nn], w1 = ws[2 * kk + 1][nn];
            __nv_bfloat16 h0 = __float2bfloat16_rn(w0), h1 = __float2bfloat16_rn(w1);
            __nv_bfloat16 l0 = __float2bfloat16_rn(w0 - __bfloat162float(h0));
            __nv_bfloat16 l1 = __float2bfloat16_rn(w1 - __bfloat162float(h1));
            uint32_t off = (uint32_t)nn * LDB + (uint32_t)(kb + 2 * kk) * 2;
            *(uint32_t*)(g_Whi[t] + off) = pkbf(h0, h1);
            *(uint32_t*)(g_Wlo[t] + off) = pkbf(l0, l1);
        }
    }
}

__global__ void k_scan() {
    const int tid = threadIdx.x, warp = tid >> 5, lane = tid & 31;
    __shared__ int tot[TT];
    if (warp < TT) {
        int s = 0;
        #pragma unroll
        for (int c = 0; c < NB / 32; c++) s += g_bcount[warp * NB + c * 32 + lane];
        #pragma unroll
        for (int o = 16; o; o >>= 1) s += __shfl_xor_sync(0xffffffffu, s, o);
        if (lane == 0) tot[warp] = s;
    }
    __syncthreads();
    if (tid == 0) {
        int o = 0, tbv = 0;
        g_offsets[0] = 0; g_tileBase[0] = 0;
        for (int t = 0; t < TT; t++) {
            o += tot[t];
            g_offsets[t + 1] = o;
            tbv += (tot[t] + TILE_M - 1) / TILE_M;
            g_tileBase[t + 1] = tbv;
        }
    }
    __syncthreads();
    if (warp < TT) {
        int run = g_offsets[warp];
        #pragma unroll
        for (int c = 0; c < NB / 32; c++) {
            int v = g_bcount[warp * NB + c * 32 + lane];
            int xsc = v;
            #pragma unroll
            for (int o = 1; o < 32; o <<= 1) {
                int y = __shfl_up_sync(0xffffffffu, xsc, o);
                if (lane >= o) xsc += y;
            }
            g_bbase[warp * NB + c * 32 + lane] = run + xsc - v;
            run += __shfl_sync(0xffffffffu, xsc, 31);
        }
    }
}

__global__ void k_scatter(const int* __restrict__ xt, int n, int seg) {
    const int bid = blockIdx.x, tid = threadIdx.x, lane = tid & 31;
    const int start = bid * seg, end = min(start + seg, n);
    __shared__ int cur[TT];
    if (tid < TT) cur[tid] = g_bbase[tid * NB + bid];
    __syncthreads();
    const int rounds = (seg + BT - 1) / BT;
    for (int r = 0; r < rounds; r++) {
        int i = start + r * BT + tid;
        int m = (i < end) ? xt[i] : -1;
        #pragma unroll
        for (int t = 0; t < TT; t++) {
            unsigned mask = __ballot_sync(0xffffffffu, m == t);
            if (mask) {
                int leader = __ffs(mask) - 1;
                int pos = 0;
                if (lane == leader) pos = atomicAdd(&cur[t], __popc(mask));
                pos = __shfl_sync(0xffffffffu, pos, leader);
                if (m == t) g_perm[pos + __popc(mask & ((1u << lane) - 1u))] = i;
            }
        }
    }
}

// ---------------- GEMM ----------------
__device__ __forceinline__ void copyW(int t, uint8_t* smem, int tid) {
    const uint4* shi = (const uint4*)g_Whi[t];
    const uint4* slo = (const uint4*)g_Wlo[t];
    uint4* dhi = (uint4*)(smem + S_WHI);
    uint4* dlo = (uint4*)(smem + S_WLO);
    #pragma unroll 4
    for (int i = tid; i < IMG_U4; i += GT) { dhi[i] = shi[i]; dlo[i] = slo[i]; }
}

// convert+store one x row (512B, lane-sliced) into hi/lo images at image row ir
__device__ __forceinline__ void cvtRow(uint4 vv, uint8_t* dst, int ir, int lane) {
    float4 f = *(const float4*)&vv;
    __nv_bfloat16 h0 = __float2bfloat16_rn(f.x), h1 = __float2bfloat16_rn(f.y);
    __nv_bfloat16 h2 = __float2bfloat16_rn(f.z), h3 = __float2bfloat16_rn(f.w);
    __nv_bfloat16 l0 = __float2bfloat16_rn(f.x - __bfloat162float(h0));
    __nv_bfloat16 l1 = __float2bfloat16_rn(f.y - __bfloat162float(h1));
    __nv_bfloat16 l2 = __float2bfloat16_rn(f.z - __bfloat162float(h2));
    __nv_bfloat16 l3 = __float2bfloat16_rn(f.w - __bfloat162float(h3));
    uint32_t offB = (uint32_t)ir * LDB + (uint32_t)lane * 8;
    *(uint2*)(dst + offB)        = make_uint2(pkbf(h0, h1), pkbf(h2, h3));
    *(uint2*)(dst + A_LO + offB) = make_uint2(pkbf(l0, l1), pkbf(l2, l3));
}

__global__ __launch_bounds__(GT, 1)
void k_gemm(const float* __restrict__ x,
            const float* __restrict__ b,
            float* __restrict__ out)
{
    extern __shared__ uint8_t smem[];
    const int tid  = threadIdx.x;
    const int warp = tid >> 5;
    const int lane = tid & 31;
    const bool consumer = (warp < 8);
    const int mw = warp & 3;        // consumer: m chunk of 32 rows
    const int nh = (warp >> 2) & 1; // consumer: n half (64 cols)
    const int pw = warp - 8;        // producer index 0..7

    const uint32_t sbase = smem_u32(smem);
    float* biasS = (float*)(smem + S_BIAS);
    int*   rowsS = (int*)(smem + S_ROWS);

    int tb[TT + 1], off[TT + 1];
    #pragma unroll
    for (int i = 0; i <= TT; i++) { tb[i] = g_tileBase[i]; off[i] = g_offsets[i]; }

    const int total = tb[TT];
    const int per   = (total + gridDim.x - 1) / gridDim.x;
    const int i0    = blockIdx.x * per;
    const int i1    = min(i0 + per, total);
    if (i0 >= i1) return;

    // consumer ldmatrix lane offsets (mapping proven R3-R7)
    const uint32_t aOff = (uint32_t)(mw * 32 + (lane & 15)) * LDB + (uint32_t)(lane >> 4) * 16;
    const uint32_t bOff = (uint32_t)(nh * 64 + (lane & 7) + ((lane & 16) ? 8 : 0)) * LDB
                        + (uint32_t)((lane >> 3) & 1) * 16;

    float acc[2][8][4];
    #pragma unroll
    for (int s = 0; s < 2; s++)
        #pragma unroll
        for (int j = 0; j < 8; j++)
            #pragma unroll
            for (int q = 0; q < 4; q++) acc[s][j][q] = 0.f;

    int cur_type;

    // ---- prologue: stage tile i0 (all warps; each stages 8 rows, batched LDG) ----
    {
        int t = 0;
        #pragma unroll
        for (int s = 1; s < TT; s++) t += (i0 >= tb[s]);
        copyW(t, smem, tid); cur_type = t;
        int segStart = off[t] + (i0 - tb[t]) * TILE_M;
        int nr       = min(TILE_M, off[t + 1] - segStart);
        if (tid < DIM) {
            rowsS[(i0 & 1) * DIM + tid] = (tid < nr) ? g_perm[segStart + tid] : -1;
            biasS[(i0 & 1) * DIM + tid] = b[(size_t)t * DIM + tid];
        }
        int rown = -1;
        if (lane < 8) {
            int idx = warp * 8 + lane;
            rown = (idx < nr) ? g_perm[segStart + idx] : -1;
        }
        uint4 v[8];
        #pragma unroll
        for (int rr = 0; rr < 8; rr++) {
            int row = __shfl_sync(0xffffffffu, rown, rr);
            v[rr] = make_uint4(0, 0, 0, 0);
            if (row >= 0) v[rr] = ((const uint4*)x)[(size_t)row * 32 + lane];
        }
        uint8_t* dst = smem + ((i0 & 1) ? S_A1 : S_A0);
        #pragma unroll
        for (int rr = 0; rr < 8; rr++) cvtRow(v[rr], dst, warp * 8 + rr, lane);
        __syncthreads();
    }

    for (int i = i0; i < i1; i++) {
        const int cb = i & 1;
        int nt = cur_type;
        if (i + 1 < i1) {
            nt = 0;
            #pragma unroll
            for (int s = 1; s < TT; s++) nt += ((i + 1) >= tb[s]);
        }

        if (consumer) {
            // ---- MMA: 3 products x 8 k-steps, m32 x n64 ----
            #pragma unroll
            for (int p = 0; p < 3; p++) {
                const uint32_t aBase = sbase + (cb ? S_A1 : S_A0) + (p == 2 ? A_LO : 0) + aOff;
                const uint32_t bBase = sbase + (p == 1 ? S_WLO : S_WHI) + bOff;
                #pragma unroll
                for (int kk = 0; kk < 8; kk++) {
                    uint32_t a0[4], a1[4];
                    ldsm4(a0, aBase + kk * 32);
                    ldsm4(a1, aBase + 16 * LDB + kk * 32);
                    #pragma unroll
                    for (int jj = 0; jj < 4; jj++) {
                        uint32_t bb[4];
                        ldsm4(bb, bBase + (uint32_t)jj * (16 * LDB) + kk * 32);
                        mma16816(acc[0][2 * jj],     a0, bb[0], bb[1]);
                        mma16816(acc[0][2 * jj + 1], a0, bb[2], bb[3]);
                        mma16816(acc[1][2 * jj],     a1, bb[0], bb[1]);
                        mma16816(acc[1][2 * jj + 1], a1, bb[2], bb[3]);
                    }
                }
            }
            // ---- epilogue (before sync: rowsS/biasS slot cb is stable) ----
            const int g = lane >> 2;
            const float* bS = biasS + cb * DIM;
            #pragma unroll
            for (int s = 0; s < 2; s++) {
                const int rbase = mw * 32 + s * 16 + g;
                const int r1 = rowsS[cb * DIM + rbase];
                const int r2 = rowsS[cb * DIM + rbase + 8];
                #pragma unroll
                for (int j = 0; j < 8; j++) {
                    int col = nh * 64 + j * 8 + (lane & 3) * 2;
                    float2 bb = *(const float2*)(bS + col);
                    if (r1 >= 0)
                        *(float2*)(out + (size_t)r1 * DIM + col) =
                            make_float2(acc[s][j][0] + bb.x, acc[s][j][1] + bb.y);
                    if (r2 >= 0)
                        *(float2*)(out + (size_t)r2 * DIM + col) =
                            make_float2(acc[s][j][2] + bb.x, acc[s][j][3] + bb.y);
                    acc[s][j][0] = acc[s][j][1] = acc[s][j][2] = acc[s][j][3] = 0.f;
                }
            }
        } else if (i + 1 < i1) {
            // ---- producer: stage tile i+1 into buffer cb^1 ----
            // Two waves of 8 batched LDG.128 (v[8] = 32 regs; MLP=8, no spills).
            int segStart = off[nt] + (i + 1 - tb[nt]) * TILE_M;
            int nr       = min(TILE_M, off[nt + 1] - segStart);
            int ptid = tid - 256;
            if (ptid < DIM) {
                rowsS[(cb ^ 1) * DIM + ptid] = (ptid < nr) ? g_perm[segStart + ptid] : -1;
                biasS[(cb ^ 1) * DIM + ptid] = b[(size_t)nt * DIM + ptid];
            }
            int rown = -1;
            if (lane < 16) {
                int idx = pw * 16 + lane;
                rown = (idx < nr) ? g_perm[segStart + idx] : -1;
            }
            uint8_t* dst = smem + ((cb ^ 1) ? S_A1 : S_A0);
            uint4 v[8];
            #pragma unroll
            for (int w = 0; w < 2; w++) {
                // wave w: batch 8 loads, then convert
                #pragma unroll
                for (int rr = 0; rr < 8; rr++) {
                    int row = __shfl_sync(0xffffffffu, rown, w * 8 + rr);
                    v[rr] = make_uint4(0, 0, 0, 0);
                    if (row >= 0) v[rr] = ((const uint4*)x)[(size_t)row * 32 + lane];
                }
                #pragma unroll
                for (int rr = 0; rr < 8; rr++)
                    cvtRow(v[rr], dst, pw * 16 + w * 8 + rr, lane);
            }
        }

        __syncthreads();
        if (nt != cur_type) {     // rare W reload: consumers done with tile i now
            copyW(nt, smem, tid);
            cur_type = nt;
            __syncthreads();
        }
    }
}

// ---------------- launch ----------------
extern "C" void kernel_launch(void* const* d_in, const int* in_sizes, int n_in,
                              void* d_out, int out_size)
{
    const float* x      = (const float*)d_in[0];
    const int*   x_type = (const int*)d_in[1];
    const float* W      = (const float*)d_in[2];
    const float* b      = (const float*)d_in[3];
    float*       out    = (float*)d_out;

    const int N   = in_sizes[1];
    const int seg = (N + NB - 1) / NB;

    static int nsm = 0;
    if (!nsm) {
        cudaDeviceGetAttribute(&nsm, cudaDevAttrMultiProcessorCount, 0);
        if (nsm <= 0) nsm = 148;
        cudaFuncSetAttribute(k_gemm, cudaFuncAttributeMaxDynamicSharedMemorySize, S_TOTAL);
    }

    k_pre<<<NB + PREPB, BT>>>(x_type, W, N, seg);
    k_scan<<<1, 256>>>();
    k_scatter<<<NB, BT>>>(x_type, N, seg);
    k_gemm<<<nsm, GT, S_TOTAL>>>(x, b, out);
}

// round 13
// speedup vs baseline: 1.3889x; 1.3815x over previous
#include <cuda_runtime.h>
#include <cuda_bf16.h>
#include <cstdint>

// HeteLinear: out[n] = x[n] @ W[x_type[n]] + b[x_type[n]]
// N=262144, IN=OUT=128, T=8, fp32.
// Grouped GEMM on mma.sync HMMA bf16, 3-product bf16 hi/lo split.
// R13 (= R10 resubmit; R12 was an infra failure, kernel never ran):
// TILE_M=64, depth-2 pipeline with CROSS-ITERATION register holding:
// producers load tile i+2's rows at iteration i and convert them at iteration
// i+1 — the load->use distance spans a barrier + full consumer phase, so DRAM
// latency is structurally hidden (no reliance on ptxas batching; v[8]=32 regs).

#define NMAX    262144
#define TT      8
#define DIM     128
#define TILE_M  64
#define GT      512
#define NB      256                 // compaction blocks
#define BT      256
#define PREPB   32                  // prep blocks appended to k_pre grid
#define LDE     136                 // padded image row (bf16 elems): 272B
#define LDB     (LDE * 2)
#define IMG_BYTES (DIM * LDE * 2)   // W image: 128 rows -> 34816
#define IMG_U4    (IMG_BYTES / 16)

// gemm smem layout (bytes). A buffer = hi(17408) + lo(17408) = 34816.
#define A_LO    17408
#define S_A0    0
#define S_A1    34816
#define S_WHI   69632
#define S_WLO   104448
#define S_BIAS  139264              // float[8][128] = 4096 (all types)
#define S_ROWS  143360              // int[2][64] = 512
#define S_TOTAL 143872

// ---------------- device globals ----------------
__device__ int g_bcount[TT * NB];
__device__ int g_bbase[TT * NB];
__device__ int g_offsets[TT + 1];
__device__ int g_tileBase[TT + 1];
__device__ int g_perm[NMAX];
__device__ __align__(16) uint8_t g_Whi[TT][IMG_BYTES];
__device__ __align__(16) uint8_t g_Wlo[TT][IMG_BYTES];

// ---------------- helpers ----------------
__device__ __forceinline__ uint32_t smem_u32(const void* p) {
    uint32_t a;
    asm("{ .reg .u64 t; cvta.to.shared.u64 t, %1; cvt.u32.u64 %0, t; }" : "=r"(a) : "l"(p));
    return a;
}
__device__ __forceinline__ void ldsm4(uint32_t (&r)[4], uint32_t addr) {
    asm volatile("ldmatrix.sync.aligned.m8n8.x4.shared.b16 {%0,%1,%2,%3}, [%4];"
                 : "=r"(r[0]), "=r"(r[1]), "=r"(r[2]), "=r"(r[3]) : "r"(addr));
}
__device__ __forceinline__ void mma16816(float (&c)[4], const uint32_t (&a)[4],
                                         uint32_t b0, uint32_t b1) {
    asm volatile("mma.sync.aligned.m16n8k16.row.col.f32.bf16.bf16.f32 "
                 "{%0,%1,%2,%3}, {%4,%5,%6,%7}, {%8,%9}, {%0,%1,%2,%3};"
                 : "+f"(c[0]), "+f"(c[1]), "+f"(c[2]), "+f"(c[3])
                 : "r"(a[0]), "r"(a[1]), "r"(a[2]), "r"(a[3]), "r"(b0), "r"(b1));
}
__device__ __forceinline__ uint32_t pkbf(__nv_bfloat16 a, __nv_bfloat16 b) {
    return (uint32_t)__bfloat16_as_ushort(a) | ((uint32_t)__bfloat16_as_ushort(b) << 16);
}

// ---------------- pre: count (blocks 0..NB-1) + W prep (blocks NB..NB+31) ----------------
__global__ void k_pre(const int* __restrict__ xt, const float* __restrict__ W,
                      int n, int seg) {
    __shared__ float ws[32][129];
    const int tid = threadIdx.x, lane = tid & 31;

    if (blockIdx.x < NB) {
        const int bid = blockIdx.x;
        const int start = bid * seg, end = min(start + seg, n);
        __shared__ int cnt[TT];
        if (tid < TT) cnt[tid] = 0;
        __syncthreads();
        int rc[TT];
        #pragma unroll
        for (int t = 0; t < TT; t++) rc[t] = 0;
        const int rounds = (seg + BT - 1) / BT;
        for (int r = 0; r < rounds; r++) {
            int i = start + r * BT + tid;
            int m = (i < end) ? xt[i] : -1;
            #pragma unroll
            for (int t = 0; t < TT; t++)
                rc[t] += __popc(__ballot_sync(0xffffffffu, m == t));
        }
        if (lane == 0) {
            #pragma unroll
            for (int t = 0; t < TT; t++) atomicAdd(&cnt[t], rc[t]);
        }
        __syncthreads();
        if (tid < TT) g_bcount[tid * NB + bid] = cnt[tid];
    } else {
        const int sl = blockIdx.x - NB;
        const int t  = sl >> 2;
        const int kb = (sl & 3) * 32;
        #pragma unroll
        for (int j = 0; j < 16; j++) {
            int idx = tid + j * 256;
            int r = idx >> 7, col = idx & 127;
            ws[r][col] = W[((size_t)t * DIM + kb + r) * DIM + col];
        }
        __syncthreads();
        const int kk = tid & 15;
        #pragma unroll
        for (int j = 0; j < 8; j++) {
            int nn = (tid >> 4) + j * 16;
            float w0 = ws[2 * kk][nn], w1 = ws[2 * kk + 1][nn];
            __nv_bfloat16 h0 = __float2bfloat16_rn(w0), h1 = __float2bfloat16_rn(w1);
            __nv_bfloat16 l0 = __float2bfloat16_rn(w0 - __bfloat162float(h0));
            __nv_bfloat16 l1 = __float2bfloat16_rn(w1 - __bfloat162float(h1));
            uint32_t off = (uint32_t)nn * LDB + (uint32_t)(kb + 2 * kk) * 2;
            *(uint32_t*)(g_Whi[t] + off) = pkbf(h0, h1);
            *(uint32_t*)(g_Wlo[t] + off) = pkbf(l0, l1);
        }
    }
}

__global__ void k_scan() {
    const int tid = threadIdx.x, warp = tid >> 5, lane = tid & 31;
    __shared__ int tot[TT];
    if (warp < TT) {
        int s = 0;
        #pragma unroll
        for (int c = 0; c < NB / 32; c++) s += g_bcount[warp * NB + c * 32 + lane];
        #pragma unroll
        for (int o = 16; o; o >>= 1) s += __shfl_xor_sync(0xffffffffu, s, o);
        if (lane == 0) tot[warp] = s;
    }
    __syncthreads();
    if (tid == 0) {
        int o = 0, tbv = 0;
        g_offsets[0] = 0; g_tileBase[0] = 0;
        for (int t = 0; t < TT; t++) {
            o += tot[t];
            g_offsets[t + 1] = o;
            tbv += (tot[t] + TILE_M - 1) / TILE_M;
            g_tileBase[t + 1] = tbv;
        }
    }
    __syncthreads();
    if (warp < TT) {
        int run = g_offsets[warp];
        #pragma unroll
        for (int c = 0; c < NB / 32; c++) {
            int v = g_bcount[warp * NB + c * 32 + lane];
            int xsc = v;
            #pragma unroll
            for (int o = 1; o < 32; o <<= 1) {
                int y = __shfl_up_sync(0xffffffffu, xsc, o);
                if (lane >= o) xsc += y;
            }
            g_bbase[warp * NB + c * 32 + lane] = run + xsc - v;
            run += __shfl_sync(0xffffffffu, xsc, 31);
        }
    }
}

__global__ void k_scatter(const int* __restrict__ xt, int n, int seg) {
    const int bid = blockIdx.x, tid = threadIdx.x, lane = tid & 31;
    const int start = bid * seg, end = min(start + seg, n);
    __shared__ int cur[TT];
    if (tid < TT) cur[tid] = g_bbase[tid * NB + bid];
    __syncthreads();
    const int rounds = (seg + BT - 1) / BT;
    for (int r = 0; r < rounds; r++) {
        int i = start + r * BT + tid;
        int m = (i < end) ? xt[i] : -1;
        #pragma unroll
        for (int t = 0; t < TT; t++) {
            unsigned mask = __ballot_sync(0xffffffffu, m == t);
            if (mask) {
                int leader = __ffs(mask) - 1;
                int pos = 0;
                if (lane == leader) pos = atomicAdd(&cur[t], __popc(mask));
                pos = __shfl_sync(0xffffffffu, pos, leader);
                if (m == t) g_perm[pos + __popc(mask & ((1u << lane) - 1u))] = i;
            }
        }
    }
}

// ---------------- GEMM ----------------
__device__ __forceinline__ void copyW(int t, uint8_t* smem, int tid) {
    const uint4* shi = (const uint4*)g_Whi[t];
    const uint4* slo = (const uint4*)g_Wlo[t];
    uint4* dhi = (uint4*)(smem + S_WHI);
    uint4* dlo = (uint4*)(smem + S_WLO);
    #pragma unroll 4
    for (int i = tid; i < IMG_U4; i += GT) { dhi[i] = shi[i]; dlo[i] = slo[i]; }
}

// convert+store one x row (512B, lane-sliced) into hi/lo halves of an A buffer
__device__ __forceinline__ void cvtRow(uint4 vv, uint8_t* dst, int ir, int lane) {
    float4 f = *(const float4*)&vv;
    __nv_bfloat16 h0 = __float2bfloat16_rn(f.x), h1 = __float2bfloat16_rn(f.y);
    __nv_bfloat16 h2 = __float2bfloat16_rn(f.z), h3 = __float2bfloat16_rn(f.w);
    __nv_bfloat16 l0 = __float2bfloat16_rn(f.x - __bfloat162float(h0));
    __nv_bfloat16 l1 = __float2bfloat16_rn(f.y - __bfloat162float(h1));
    __nv_bfloat16 l2 = __float2bfloat16_rn(f.z - __bfloat162float(h2));
    __nv_bfloat16 l3 = __float2bfloat16_rn(f.w - __bfloat162float(h3));
    uint32_t offB = (uint32_t)ir * LDB + (uint32_t)lane * 8;
    *(uint2*)(dst + offB)        = make_uint2(pkbf(h0, h1), pkbf(h2, h3));
    *(uint2*)(dst + A_LO + offB) = make_uint2(pkbf(l0, l1), pkbf(l2, l3));
}

__global__ __launch_bounds__(GT, 1)
void k_gemm(const float* __restrict__ x,
            const float* __restrict__ b,
            float* __restrict__ out)
{
    extern __shared__ uint8_t smem[];
    const int tid  = threadIdx.x;
    const int warp = tid >> 5;
    const int lane = tid & 31;
    const bool consumer = (warp < 8);
    const int mw = warp & 1;        // consumer: m chunk of 32 rows (0..1)
    const int nq = warp >> 1;       // consumer: n quarter of 32 cols (0..3)
    const int pw = warp - 8;        // producer index 0..7

    const uint32_t sbase = smem_u32(smem);
    float* biasAll = (float*)(smem + S_BIAS);   // [8][128]
    int*   rowsS   = (int*)(smem + S_ROWS);     // [2][64]

    int tb[TT + 1], off[TT + 1];
    #pragma unroll
    for (int i = 0; i <= TT; i++) { tb[i] = g_tileBase[i]; off[i] = g_offsets[i]; }

    const int total = tb[TT];
    const int per   = (total + gridDim.x - 1) / gridDim.x;
    const int i0    = blockIdx.x * per;
    const int i1    = min(i0 + per, total);
    if (i0 >= i1) return;

    // consumer ldmatrix lane offsets (mapping proven R3-R9)
    const uint32_t aOff = (uint32_t)(mw * 32 + (lane & 15)) * LDB + (uint32_t)(lane >> 4) * 16;
    const uint32_t bOff = (uint32_t)(nq * 32 + (lane & 7) + ((lane & 16) ? 8 : 0)) * LDB
                        + (uint32_t)((lane >> 3) & 1) * 16;

    float acc[2][4][4];
    #pragma unroll
    for (int s = 0; s < 2; s++)
        #pragma unroll
        for (int j = 0; j < 4; j++)
            #pragma unroll
            for (int q = 0; q < 4; q++) acc[s][j][q] = 0.f;

    int cur_type;
    int rown = -1;          // producer: perm indices (lane<8) for NEXT staged tile
    uint4 v[8];             // producer: raw x rows for NEXT staged tile (held)

    // ---- prologue ----
    {
        int t = 0;
        #pragma unroll
        for (int s = 1; s < TT; s++) t += (i0 >= tb[s]);
        cur_type = t;
        copyW(t, smem, tid);
        // all biases into smem once
        for (int c = tid; c < TT * DIM; c += GT) biasAll[c] = b[c];

        if (!consumer) {
            // stage tile i0 synchronously
            int segStart = off[t] + (i0 - tb[t]) * TILE_M;
            int nr       = min(TILE_M, off[t + 1] - segStart);
            int r0 = -1;
            if (lane < 8) {
                int idx = pw * 8 + lane;
                r0 = (idx < nr) ? g_perm[segStart + idx] : -1;
                rowsS[(i0 & 1) * TILE_M + idx] = r0;
            }
            uint8_t* dst = smem + ((i0 & 1) ? S_A1 : S_A0);
            #pragma unroll
            for (int rr = 0; rr < 8; rr++) {
                int row = __shfl_sync(0xffffffffu, r0, rr);
                uint4 vv = make_uint4(0, 0, 0, 0);
                if (row >= 0) vv = ((const uint4*)x)[(size_t)row * 32 + lane];
                cvtRow(vv, dst, pw * 8 + rr, lane);
            }
            // preload tile i0+1 into held regs
            rown = -1;
            #pragma unroll
            for (int rr = 0; rr < 8; rr++) v[rr] = make_uint4(0, 0, 0, 0);
            if (i0 + 1 < i1) {
                int nt1 = 0;
                #pragma unroll
                for (int s = 1; s < TT; s++) nt1 += ((i0 + 1) >= tb[s]);
                int ss = off[nt1] + (i0 + 1 - tb[nt1]) * TILE_M;
                int nr1 = min(TILE_M, off[nt1 + 1] - ss);
                if (lane < 8) {
                    int idx = pw * 8 + lane;
                    rown = (idx < nr1) ? g_perm[ss + idx] : -1;
                }
                #pragma unroll
                for (int rr = 0; rr < 8; rr++) {
                    int row = __shfl_sync(0xffffffffu, rown, rr);
                    if (row >= 0) v[rr] = ((const uint4*)x)[(size_t)row * 32 + lane];
                }
            }
        }
        __syncthreads();
    }

    for (int i = i0; i < i1; i++) {
        const int cb = i & 1;
        int nt = cur_type;                    // type of tile i+1 (uniform)
        if (i + 1 < i1) {
            nt = 0;
            #pragma unroll
            for (int s = 1; s < TT; s++) nt += ((i + 1) >= tb[s]);
        }

        if (consumer) {
            int t = 0;                        // this tile's type (for bias)
            #pragma unroll
            for (int s = 1; s < TT; s++) t += (i >= tb[s]);
            // ---- MMA: 3 products x 8 k-steps, m32 x n32 ----
            #pragma unroll
            for (int p = 0; p < 3; p++) {
                const uint32_t aBase = sbase + (cb ? S_A1 : S_A0) + (p == 2 ? A_LO : 0) + aOff;
                const uint32_t bBase = sbase + (p == 1 ? S_WLO : S_WHI) + bOff;
                #pragma unroll
                for (int kk = 0; kk < 8; kk++) {
                    uint32_t a0[4], a1[4];
                    ldsm4(a0, aBase + kk * 32);
                    ldsm4(a1, aBase + 16 * LDB + kk * 32);
                    #pragma unroll
                    for (int jj = 0; jj < 2; jj++) {
                        uint32_t bb[4];
                        ldsm4(bb, bBase + (uint32_t)jj * (16 * LDB) + kk * 32);
                        mma16816(acc[0][2 * jj],     a0, bb[0], bb[1]);
                        mma16816(acc[0][2 * jj + 1], a0, bb[2], bb[3]);
                        mma16816(acc[1][2 * jj],     a1, bb[0], bb[1]);
                        mma16816(acc[1][2 * jj + 1], a1, bb[2], bb[3]);
                    }
                }
            }
            // ---- epilogue (rowsS slot cb stable until the barrier) ----
            const int g = lane >> 2;
            const float* bS = biasAll + t * DIM;
            #pragma unroll
            for (int s = 0; s < 2; s++) {
                const int rbase = mw * 32 + s * 16 + g;
                const int r1 = rowsS[cb * TILE_M + rbase];
                const int r2 = rowsS[cb * TILE_M + rbase + 8];
                #pragma unroll
                for (int j = 0; j < 4; j++) {
                    int col = nq * 32 + j * 8 + (lane & 3) * 2;
                    float2 bb = *(const float2*)(bS + col);
                    if (r1 >= 0)
                        *(float2*)(out + (size_t)r1 * DIM + col) =
                            make_float2(acc[s][j][0] + bb.x, acc[s][j][1] + bb.y);
                    if (r2 >= 0)
                        *(float2*)(out + (size_t)r2 * DIM + col) =
                            make_float2(acc[s][j][2] + bb.x, acc[s][j][3] + bb.y);
                    acc[s][j][0] = acc[s][j][1] = acc[s][j][2] = acc[s][j][3] = 0.f;
                }
            }
        } else {
            // ---- producer: convert held tile i+1, then load tile i+2 ----
            if (i + 1 < i1) {
                uint8_t* dst = smem + ((cb ^ 1) ? S_A1 : S_A0);
                #pragma unroll
                for (int rr = 0; rr < 8; rr++)
                    cvtRow(v[rr], dst, pw * 8 + rr, lane);
                if (lane < 8)
                    rowsS[(cb ^ 1) * TILE_M + pw * 8 + lane] = rown;
            }
            asm volatile("" ::: "memory");   // keep loads below converts
            rown = -1;
            #pragma unroll
            for (int rr = 0; rr < 8; rr++) v[rr] = make_uint4(0, 0, 0, 0);
            if (i + 2 < i1) {
                int nt2 = 0;
                #pragma unroll
                for (int s = 1; s < TT; s++) nt2 += ((i + 2) >= tb[s]);
                int ss = off[nt2] + (i + 2 - tb[nt2]) * TILE_M;
                int nr2 = min(TILE_M, off[nt2 + 1] - ss);
                if (lane < 8) {
                    int idx = pw * 8 + lane;
                    rown = (idx < nr2) ? g_perm[ss + idx] : -1;
                }
                #pragma unroll
                for (int rr = 0; rr < 8; rr++) {
                    int row = __shfl_sync(0xffffffffu, rown, rr);
                    if (row >= 0) v[rr] = ((const uint4*)x)[(size_t)row * 32 + lane];
                }
            }
        }

        __syncthreads();
        if (nt != cur_type) {     // rare W reload (type boundary)
            copyW(nt, smem, tid);
            cur_type = nt;
            __syncthreads();
        }
    }
}

// ---------------- launch ----------------
extern "C" void kernel_launch(void* const* d_in, const int* in_sizes, int n_in,
                              void* d_out, int out_size)
{
    const float* x      = (const float*)d_in[0];
    const int*   x_type = (const int*)d_in[1];
    const float* W      = (const float*)d_in[2];
    const float* b      = (const float*)d_in[3];
    float*       out    = (float*)d_out;

    const int N   = in_sizes[1];
    const int seg = (N + NB - 1) / NB;

    static int nsm = 0;
    if (!nsm) {
        cudaDeviceGetAttribute(&nsm, cudaDevAttrMultiProcessorCount, 0);
        if (nsm <= 0) nsm = 148;
        cudaFuncSetAttribute(k_gemm, cudaFuncAttributeMaxDynamicSharedMemorySize, S_TOTAL);
    }

    k_pre<<<NB + PREPB, BT>>>(x_type, W, N, seg);
    k_scan<<<1, 256>>>();
    k_scatter<<<NB, BT>>>(x_type, N, seg);
    k_gemm<<<nsm, GT, S_TOTAL>>>(x, b, out);
}